// round 15
// baseline (speedup 1.0000x reference)
#include <cuda_runtime.h>
#include <math.h>
#include <stdint.h>

#define MAXN 20000

// ---------------- scratch (static device memory; no allocs) ----------------
__device__ float4 g_ah_src[MAXN * 34];   // 34 rows/node, row 33 = zero pad
__device__ float4 g_ah_dst[MAXN * 34];
__device__ float  g_as_src[MAXN * 64];   // includes folded w1_wsb bias
__device__ float  g_as_dst[MAXN * 64];
__device__ float  g_s_acc[MAXN * 64];
__device__ float  g_v_acc[MAXN * 12];
__device__ float  g_cnt[MAXN];
__device__ unsigned g_ticket;
__device__ unsigned g_bar;               // monotonic ticket barrier (replay-safe)

// ---------------- shared-memory weight layout (float indices) ----------------
#define O_WES   0
#define O_WVN   (O_WES + 32*72)
#define O_B1    (O_WVN + 34*72)
#define O_WHE   (O_B1 + 64)
#define O_WV1   (O_WHE + 36)
#define O_WSV1  (O_WV1 + 136)
#define O_BSV1  (O_WSV1 + 256)
#define O_W2H   (O_BSV1 + 4)
#define O_W2S   (O_W2H + 16)
#define O_B2    (O_W2S + 68*72)
#define O_WV2   (O_B2 + 64)
#define O_WSV2  (O_WV2 + 16)
#define O_BSV2  (O_WSV2 + 256)
#define O_W3H   (O_BSV2 + 4)
#define O_W3S   (O_W3H + 16)
#define O_B3    (O_W3S + 68*72)
#define O_WV3   (O_B3 + 64)
#define O_WSV3  (O_WV3 + 16)
#define O_BSV3  (O_WSV3 + 256)
#define SMEM_FLOATS (O_BSV3 + 4)
#define SMEM_BYTES (SMEM_FLOATS * 4)

typedef unsigned long long ull;

__device__ __forceinline__ float fsig(float x) {
    float t;
    asm("ex2.approx.f32 %0, %1;" : "=f"(t) : "f"(x * -1.4426950408889634f));
    float r;
    asm("rcp.approx.f32 %0, %1;" : "=f"(r) : "f"(t + 1.0f));
    return r;
}
__device__ __forceinline__ float fsqrt_(float x) {
    float r;
    asm("sqrt.approx.f32 %0, %1;" : "=f"(r) : "f"(x));
    return r;
}
__device__ __forceinline__ ull pack2(float lo, float hi) {
    ull r;
    asm("mov.b64 %0, {%1, %2};" : "=l"(r) : "f"(lo), "f"(hi));
    return r;
}
__device__ __forceinline__ void unpack2(float& lo, float& hi, ull a) {
    asm("mov.b64 {%0, %1}, %2;" : "=f"(lo), "=f"(hi) : "l"(a));
}
__device__ __forceinline__ ull add2(ull a, ull b) {
    ull r;
    asm("add.rn.f32x2 %0, %1, %2;" : "=l"(r) : "l"(a), "l"(b));
    return r;
}

__device__ __forceinline__ void fma_row32(ull acc[16], float x, const float* row) {
    ull xx = pack2(x, x);
    const ulonglong2* r2 = (const ulonglong2*)row;
#pragma unroll
    for (int j = 0; j < 8; j++) {
        ulonglong2 w = r2[j];
        asm("fma.rn.f32x2 %0, %1, %2, %0;" : "+l"(acc[2*j])   : "l"(xx), "l"(w.x));
        asm("fma.rn.f32x2 %0, %1, %2, %0;" : "+l"(acc[2*j+1]) : "l"(xx), "l"(w.y));
    }
}

// ---------------- GVP layer for layers 2/3 (64 scalars split over lane pair) ----------------
__device__ __forceinline__ void gvp64(
    int p, const float* sm, const float sf_in[32], const float vin[12],
    float sf_out[32], float vout[12],
    int o_wh, int o_ws, int o_b, int o_wv, int o_wsv, int o_bsv, bool final_)
{
    float vh[12];
#pragma unroll
    for (int h = 0; h < 4; h++) {
        float x = 0.f, y = 0.f, z = 0.f;
#pragma unroll
        for (int o = 0; o < 4; o++) {
            float w = sm[o_wh + o * 4 + h];
            x += vin[o*3+0] * w; y += vin[o*3+1] * w; z += vin[o*3+2] * w;
        }
        vh[h*3+0] = x; vh[h*3+1] = y; vh[h*3+2] = z;
    }
    float vn2[4];
#pragma unroll
    for (int h = 0; h < 4; h++)
        vn2[h] = fsqrt_(fmaxf(vh[h*3]*vh[h*3] + vh[h*3+1]*vh[h*3+1] + vh[h*3+2]*vh[h*3+2], 1e-8f));
    float vo2[12];
#pragma unroll
    for (int o = 0; o < 4; o++) {
        float x = 0.f, y = 0.f, z = 0.f;
#pragma unroll
        for (int h = 0; h < 4; h++) {
            float w = sm[o_wv + h * 4 + o];
            x += vh[h*3+0] * w; y += vh[h*3+1] * w; z += vh[h*3+2] * w;
        }
        vo2[o*3+0] = x; vo2[o*3+1] = y; vo2[o*3+2] = z;
    }
    ull acc[16];
    {
        const ulonglong2* B = (const ulonglong2*)(sm + o_b + 32 * p);
#pragma unroll
        for (int j = 0; j < 8; j++) {
            ulonglong2 b = B[j];
            acc[2*j]   = b.x;
            acc[2*j+1] = b.y;
        }
    }
    const float* W = sm + o_ws;
    int half = 36 * p;
#pragma unroll
    for (int r = 0; r < 32; r++) {
        float mine  = sf_in[r];
        float other = __shfl_xor_sync(0xffffffffu, mine, 1);
        float klo = p ? other : mine;
        float khi = p ? mine  : other;
        fma_row32(acc, klo, W + r * 72 + half);
        fma_row32(acc, khi, W + (32 + r) * 72 + half);
    }
#pragma unroll
    for (int h = 0; h < 4; h++)
        fma_row32(acc, vn2[h], W + (64 + h) * 72 + half);
#pragma unroll
    for (int j = 0; j < 16; j++) unpack2(sf_out[2*j], sf_out[2*j+1], acc[j]);

    ull P01 = 0, P23 = 0;
    {
        const ulonglong2* WSV = (const ulonglong2*)(sm + o_wsv + 32 * p * 4);
#pragma unroll
        for (int r = 0; r < 32; r++) {
            float t = final_ ? sf_out[r] : fsig(sf_out[r]);
            ull tt = pack2(t, t);
            ulonglong2 w = WSV[r];
            asm("fma.rn.f32x2 %0, %1, %2, %0;" : "+l"(P01) : "l"(tt), "l"(w.x));
            asm("fma.rn.f32x2 %0, %1, %2, %0;" : "+l"(P23) : "l"(tt), "l"(w.y));
        }
    }
    float p0, p1, p2, p3;
    unpack2(p0, p1, P01);
    unpack2(p2, p3, P23);
    float g0 = fsig(sm[o_bsv+0] + p0 + __shfl_xor_sync(0xffffffffu, p0, 1));
    float g1 = fsig(sm[o_bsv+1] + p1 + __shfl_xor_sync(0xffffffffu, p1, 1));
    float g2 = fsig(sm[o_bsv+2] + p2 + __shfl_xor_sync(0xffffffffu, p2, 1));
    float g3 = fsig(sm[o_bsv+3] + p3 + __shfl_xor_sync(0xffffffffu, p3, 1));
#pragma unroll
    for (int c = 0; c < 3; c++) {
        vout[0*3+c] = vo2[0*3+c] * g0;
        vout[1*3+c] = vo2[1*3+c] * g1;
        vout[2*3+c] = vo2[2*3+c] * g2;
        vout[3*3+c] = vo2[3*3+c] * g3;
    }
    if (!final_) {
#pragma unroll
        for (int r = 0; r < 32; r++) sf_out[r] = fmaxf(sf_out[r], 0.f);
    }
}

__device__ __forceinline__ void smcopy(float* d, const float* s, int n) {
    for (int i = threadIdx.x; i < n; i += blockDim.x) d[i] = s[i];
}
__device__ __forceinline__ void smcopy_pad(float* d, const float* s, int K) {
    for (int i = threadIdx.x; i < K * 64; i += blockDim.x) {
        int k = i >> 6, c = i & 63;
        d[k * 72 + c + (c >= 32 ? 4 : 0)] = s[i];
    }
}

// -------- prep: 16 nodes per block; folds bias; zeroes ticket --------
__global__ void __launch_bounds__(128) prep_kernel(
    const float* __restrict__ node_s, const float* __restrict__ node_v,
    const float* __restrict__ w1_wh, const float* __restrict__ w1_ws,
    const float* __restrict__ w1_wsb, int N)
{
    __shared__ float xs[16 * 128];
    const int tid = threadIdx.x;
    const int n0 = blockIdx.x * 16;
    const int nmax = min(16, N - n0);
    if (blockIdx.x == 0 && tid == 0) g_ticket = 0u;

    for (int i = tid; i < 16 * 128; i += 128) {
        int b = i >> 7;
        xs[i] = (b < nmax) ? node_s[(size_t)(n0 + b) * 128 + (i & 127)] : 0.f;
    }
    for (int i = tid; i < nmax * 64; i += 128) g_s_acc[(size_t)n0 * 64 + i] = 0.f;
    for (int i = tid; i < nmax * 12; i += 128) g_v_acc[(size_t)n0 * 12 + i] = 0.f;
    if (tid < nmax) g_cnt[n0 + tid] = 0.f;
    __syncthreads();

    {
        int j = tid & 63;
        int half = tid >> 6;
        const float* W = w1_ws + (half ? 160 * 64 : 0) + j;
        float bias = half ? 0.f : w1_wsb[j];
        float acc[16];
#pragma unroll
        for (int b = 0; b < 16; b++) acc[b] = 0.f;
        const float4* xs4 = (const float4*)xs;
#pragma unroll 2
        for (int k4 = 0; k4 < 32; k4++) {
            float w0 = W[(k4*4+0)*64], w1 = W[(k4*4+1)*64];
            float w2 = W[(k4*4+2)*64], w3 = W[(k4*4+3)*64];
#pragma unroll
            for (int b = 0; b < 16; b++) {
                float4 x = xs4[b * 32 + k4];
                acc[b] += x.x * w0 + x.y * w1 + x.z * w2 + x.w * w3;
            }
        }
        float* dst = half ? g_as_dst : g_as_src;
#pragma unroll
        for (int b = 0; b < 16; b++)
            if (b < nmax) dst[(size_t)(n0 + b) * 64 + j] = acc[b] + bias;
    }
    for (int i = tid; i < 16 * 68; i += 128) {
        int b = i / 68, r = i % 68;
        if (b >= nmax) continue;
        int n = n0 + b;
        bool is_src = (r < 34);
        int h = is_src ? r : r - 34;
        float4 o = make_float4(0.f, 0.f, 0.f, 0.f);
        if (h < 33) {
            int base = is_src ? 0 : 17;
            const float* v = node_v + (size_t)n * 48;
            float x = 0.f, y = 0.f, z = 0.f;
#pragma unroll
            for (int k = 0; k < 16; k++) {
                float w = w1_wh[(base + k) * 33 + h];
                x += v[k*3+0] * w; y += v[k*3+1] * w; z += v[k*3+2] * w;
            }
            o = make_float4(x, y, z, 0.f);
        }
        if (is_src) g_ah_src[n * 34 + h] = o;
        else        g_ah_dst[n * 34 + h] = o;
    }
}

// -------- edge + fused finalize: 2 lanes per edge, ticketed; grid barrier; output --------
__global__ void __launch_bounds__(128, 3) edge_kernel(
    const int* __restrict__ ei,
    const float* __restrict__ edge_s,
    const float* __restrict__ edge_v,
    const int* __restrict__ mask,
    float* __restrict__ out, int N,
    const float* __restrict__ w1_wh, const float* __restrict__ w1_ws,
    const float* __restrict__ w1_wsb, const float* __restrict__ w1_wv,
    const float* __restrict__ w1_wsv, const float* __restrict__ w1_wsvb,
    const float* __restrict__ w2_wh, const float* __restrict__ w2_ws,
    const float* __restrict__ w2_wsb, const float* __restrict__ w2_wv,
    const float* __restrict__ w2_wsv, const float* __restrict__ w2_wsvb,
    const float* __restrict__ w3_wh, const float* __restrict__ w3_ws,
    const float* __restrict__ w3_wsb, const float* __restrict__ w3_wv,
    const float* __restrict__ w3_wsv, const float* __restrict__ w3_wsvb,
    int E)
{
    extern __shared__ float sm[];
    smcopy_pad(sm + O_WES, w1_ws + 128 * 64, 32);
    smcopy_pad(sm + O_WVN, w1_ws + 288 * 64, 33);
    for (int i = threadIdx.x; i < 72; i += blockDim.x) sm[O_WVN + 33 * 72 + i] = 0.f;
    smcopy(sm + O_B1,   w1_wsb, 64);
    smcopy(sm + O_WHE,  w1_wh + 16 * 33, 33);
    for (int i = threadIdx.x + 33; i < 36; i += blockDim.x) sm[O_WHE + i] = 0.f;
    smcopy(sm + O_WV1,  w1_wv, 132);
    for (int i = threadIdx.x + 132; i < 136; i += blockDim.x) sm[O_WV1 + i] = 0.f;
    smcopy(sm + O_WSV1, w1_wsv, 256);
    smcopy(sm + O_BSV1, w1_wsvb, 4);
    smcopy(sm + O_W2H,  w2_wh, 16);
    smcopy_pad(sm + O_W2S, w2_ws, 68);
    smcopy(sm + O_B2,   w2_wsb, 64);
    smcopy(sm + O_WV2,  w2_wv, 16);
    smcopy(sm + O_WSV2, w2_wsv, 256);
    smcopy(sm + O_BSV2, w2_wsvb, 4);
    smcopy(sm + O_W3H,  w3_wh, 16);
    smcopy_pad(sm + O_W3S, w3_ws, 68);
    smcopy(sm + O_B3,   w3_wsb, 64);
    smcopy(sm + O_WV3,  w3_wv, 16);
    smcopy(sm + O_WSV3, w3_wsv, 256);
    smcopy(sm + O_BSV3, w3_wsvb, 4);
    __syncthreads();

    const unsigned FULL = 0xffffffffu;
    const int lane = threadIdx.x & 31;
    const int p = lane & 1;
    const int wpair = lane >> 1;
    const int half = 36 * p;
    const int hs = 17 * p;
    const int hp = 17 - hs;

    unsigned t;
    {
        unsigned tt = 0;
        if (lane == 0) tt = atomicAdd(&g_ticket, 16u);
        t = __shfl_sync(FULL, tt, 0);
    }
    int P = (int)t + wpair;
    bool valid = P < E;
    int e = valid ? P : 0;
    int src = ei[e];
    int dst = ei[e + E];
    float ev0 = edge_v[e*3+0], ev1 = edge_v[e*3+1], ev2 = edge_v[e*3+2];

    while ((int)t < E) {
        unsigned t2;
        {
            unsigned tt = 0;
            if (lane == 0) tt = atomicAdd(&g_ticket, 16u);
            t2 = __shfl_sync(FULL, tt, 0);
        }
        int P2 = (int)t2 + wpair;
        bool valid2 = P2 < E;
        int e2 = valid2 ? P2 : 0;
        int src2 = ei[e2];
        int dst2 = ei[e2 + E];
        float f0 = edge_v[e2*3+0], f1 = edge_v[e2*3+1], f2 = edge_v[e2*3+2];

        // ---- layer 1 scalar acc init (bias pre-folded; packed adds)
        ull acc[16];
        {
            const ulonglong2* As = (const ulonglong2*)(g_as_src + (size_t)src * 64 + 32 * p);
            const ulonglong2* Bs = (const ulonglong2*)(g_as_dst + (size_t)dst * 64 + 32 * p);
#pragma unroll
            for (int j = 0; j < 8; j++) {
                ulonglong2 a = As[j], b = Bs[j];
                acc[2*j]   = add2(a.x, b.x);
                acc[2*j+1] = add2(a.y, b.y);
            }
        }
        // ---- edge_s rows
        {
            const float4* ES = (const float4*)(edge_s + (size_t)e * 32);
#pragma unroll
            for (int k4 = 0; k4 < 8; k4++) {
                float4 es = ES[k4];
                fma_row32(acc, es.x, sm + O_WES + (k4*4+0) * 72 + half);
                fma_row32(acc, es.y, sm + O_WES + (k4*4+1) * 72 + half);
                fma_row32(acc, es.z, sm + O_WES + (k4*4+2) * 72 + half);
                fma_row32(acc, es.w, sm + O_WES + (k4*4+3) * 72 + half);
            }
        }
        // ---- layer-1 vector path
        float vo1p[12];
#pragma unroll
        for (int i = 0; i < 12; i++) vo1p[i] = 0.f;
        {
            const float4* A = g_ah_src + (size_t)src * 34 + hs;
            const float4* B = g_ah_dst + (size_t)dst * 34 + hs;
#pragma unroll
            for (int k = 0; k < 17; k++) {
                int h = hs + k;
                float4 a = A[k];
                float4 b = B[k];
                float w = sm[O_WHE + h];
                float x = a.x + b.x + ev0 * w;
                float y = a.y + b.y + ev1 * w;
                float z = a.z + b.z + ev2 * w;
                float vn = fsqrt_(fmaxf(x*x + y*y + z*z, 1e-8f));
                float vnp = __shfl_xor_sync(FULL, vn, 1);
                fma_row32(acc, vn,  sm + O_WVN + h * 72 + half);
                fma_row32(acc, vnp, sm + O_WVN + (hp + k) * 72 + half);
                float4 wv = *(const float4*)(sm + O_WV1 + h * 4);
                vo1p[0] += wv.x * x; vo1p[1]  += wv.x * y; vo1p[2]  += wv.x * z;
                vo1p[3] += wv.y * x; vo1p[4]  += wv.y * y; vo1p[5]  += wv.y * z;
                vo1p[6] += wv.z * x; vo1p[7]  += wv.z * y; vo1p[8]  += wv.z * z;
                vo1p[9] += wv.w * x; vo1p[10] += wv.w * y; vo1p[11] += wv.w * z;
            }
        }
        float vo1[12];
#pragma unroll
        for (int i = 0; i < 12; i++)
            vo1[i] = vo1p[i] + __shfl_xor_sync(FULL, vo1p[i], 1);

        float s1f[32];
#pragma unroll
        for (int j = 0; j < 16; j++) unpack2(s1f[2*j], s1f[2*j+1], acc[j]);

        // ---- gate 1 (packed partials)
        float v1[12];
        {
            ull P01 = 0, P23 = 0;
            const ulonglong2* WSV = (const ulonglong2*)(sm + O_WSV1 + 32 * p * 4);
#pragma unroll
            for (int r = 0; r < 32; r++) {
                float tt = fsig(s1f[r]);
                ull tp = pack2(tt, tt);
                ulonglong2 w = WSV[r];
                asm("fma.rn.f32x2 %0, %1, %2, %0;" : "+l"(P01) : "l"(tp), "l"(w.x));
                asm("fma.rn.f32x2 %0, %1, %2, %0;" : "+l"(P23) : "l"(tp), "l"(w.y));
            }
            float p0, p1, p2, p3;
            unpack2(p0, p1, P01);
            unpack2(p2, p3, P23);
            float g0 = fsig(sm[O_BSV1+0] + p0 + __shfl_xor_sync(FULL, p0, 1));
            float g1 = fsig(sm[O_BSV1+1] + p1 + __shfl_xor_sync(FULL, p1, 1));
            float g2 = fsig(sm[O_BSV1+2] + p2 + __shfl_xor_sync(FULL, p2, 1));
            float g3 = fsig(sm[O_BSV1+3] + p3 + __shfl_xor_sync(FULL, p3, 1));
#pragma unroll
            for (int c = 0; c < 3; c++) {
                v1[0*3+c] = vo1[0*3+c] * g0;
                v1[1*3+c] = vo1[1*3+c] * g1;
                v1[2*3+c] = vo1[2*3+c] * g2;
                v1[3*3+c] = vo1[3*3+c] * g3;
            }
#pragma unroll
            for (int r = 0; r < 32; r++) s1f[r] = fmaxf(s1f[r], 0.f);
        }

        // ---- layers 2 and 3
        float s2f[32], v2[12];
        gvp64(p, sm, s1f, v1, s2f, v2, O_W2H, O_W2S, O_B2, O_WV2, O_WSV2, O_BSV2, false);
        float s3f[32], v3[12];
        gvp64(p, sm, s2f, v2, s3f, v3, O_W3H, O_W3S, O_B3, O_WV3, O_WSV3, O_BSV3, true);

        // ---- scatter-accumulate at dst
        if (valid) {
            float* sa = g_s_acc + (size_t)dst * 64 + 32 * p;
#pragma unroll
            for (int j = 0; j < 8; j++) {
                asm volatile("red.global.add.v4.f32 [%0], {%1, %2, %3, %4};"
                    :: "l"(sa + 4*j),
                       "f"(s3f[4*j]), "f"(s3f[4*j+1]), "f"(s3f[4*j+2]), "f"(s3f[4*j+3])
                    : "memory");
            }
            float* va = g_v_acc + (size_t)dst * 12 + 6 * p;
#pragma unroll
            for (int j = 0; j < 3; j++) {
                asm volatile("red.global.add.v2.f32 [%0], {%1, %2};"
                    :: "l"(va + 2*j), "f"(v3[6*p + 2*j]), "f"(v3[6*p + 2*j+1])
                    : "memory");
            }
            if (p == 0) atomicAdd(g_cnt + dst, 1.0f);
        }

        t = t2; e = e2; src = src2; dst = dst2;
        ev0 = f0; ev1 = f1; ev2 = f2; valid = valid2;
    }

    // ---- grid barrier (monotonic ticket; graph-replay safe) ----
    __threadfence();
    __syncthreads();
    if (threadIdx.x == 0) {
        unsigned tk = atomicAdd(&g_bar, 1u);
        unsigned target = (tk / gridDim.x + 1u) * gridDim.x;
        unsigned v;
        do {
            asm volatile("ld.acquire.gpu.u32 %0, [%1];" : "=r"(v) : "l"(&g_bar));
        } while ((int)(v - target) < 0);
    }
    __syncthreads();

    // ---- fused finalize (grid-stride) ----
    {
        const int total = N * 64 + N * 4;
        const int stride = gridDim.x * blockDim.x;
        for (int idx = blockIdx.x * blockDim.x + threadIdx.x; idx < total; idx += stride) {
            if (idx < N * 64) {
                int n = idx >> 6;
                int j = idx & 63;
                float denom = fmaxf(g_cnt[n], 1.0f);
                float s = g_s_acc[idx] / denom;
                float m = (mask[n] != 0) ? 1.0f : 0.0f;
                float val;
                if (j < 7)       val = __cosf(s);
                else if (j < 14) val = __sinf(s);
                else             val = __expf(s);
                out[idx] = val * m;
            } else {
                int k = idx - N * 64;
                int n = k >> 2;
                int o = k & 3;
                float denom = fmaxf(g_cnt[n], 1.0f);
                float x = g_v_acc[n*12 + o*3 + 0] / denom;
                float y = g_v_acc[n*12 + o*3 + 1] / denom;
                float z = g_v_acc[n*12 + o*3 + 2] / denom;
                float mag = sqrtf(x*x + y*y + z*z);
                float m = (mask[n] != 0) ? 1.0f : 0.0f;
                float sc = m / (mag + 1e-8f);
                float* vout = out + N * 64 + n * 12 + o * 3;
                vout[0] = x * sc; vout[1] = y * sc; vout[2] = z * sc;
            }
        }
    }
}

extern "C" void kernel_launch(void* const* d_in, const int* in_sizes, int n_in,
                              void* d_out, int out_size)
{
    const float* node_s = (const float*)d_in[0];
    const float* node_v = (const float*)d_in[1];
    const int*   ei     = (const int*)d_in[2];
    const float* edge_s = (const float*)d_in[3];
    const float* edge_v = (const float*)d_in[4];
    const int*   mask   = (const int*)d_in[5];
    const float* w1_wh  = (const float*)d_in[6];
    const float* w1_ws  = (const float*)d_in[7];
    const float* w1_wsb = (const float*)d_in[8];

    int N = in_sizes[0] / 128;
    int E = in_sizes[3] / 32;
    float* out = (float*)d_out;

    prep_kernel<<<(N + 15) / 16, 128>>>(node_s, node_v, w1_wh, w1_ws, w1_wsb, N);

    cudaFuncSetAttribute(edge_kernel,
                         cudaFuncAttributeMaxDynamicSharedMemorySize, SMEM_BYTES);
    edge_kernel<<<444, 128, SMEM_BYTES>>>(
        ei, edge_s, edge_v, mask, out, N,
        w1_wh, w1_ws, w1_wsb,
        (const float*)d_in[9],  (const float*)d_in[10],
        (const float*)d_in[11], (const float*)d_in[12], (const float*)d_in[13],
        (const float*)d_in[14], (const float*)d_in[15], (const float*)d_in[16],
        (const float*)d_in[17], (const float*)d_in[18], (const float*)d_in[19],
        (const float*)d_in[20], (const float*)d_in[21], (const float*)d_in[22],
        (const float*)d_in[23],
        E);
}

// round 16
// speedup vs baseline: 1.0508x; 1.0508x over previous
#include <cuda_runtime.h>
#include <math.h>
#include <stdint.h>

#define MAXN 20000

// ---------------- scratch (static device memory; no allocs) ----------------
// ah layout: per node, 2 lane-chunks of 52 floats (17 rows x 3 floats + 1 pad),
// chunk c holds rows 17c..17c+16 (row 33 is zero pad). 16B-aligned chunks.
__device__ float  g_ah_src[MAXN * 104];
__device__ float  g_ah_dst[MAXN * 104];
__device__ float  g_as_src[MAXN * 64];   // includes folded w1_wsb bias
__device__ float  g_as_dst[MAXN * 64];
__device__ float  g_s_acc[MAXN * 64];
__device__ float  g_v_acc[MAXN * 12];
__device__ float  g_cnt[MAXN];
__device__ unsigned g_ticket;

// ---------------- shared-memory weight layout (float indices) ----------------
#define O_WES   0
#define O_WVN   (O_WES + 32*72)
#define O_B1    (O_WVN + 34*72)
#define O_WHE   (O_B1 + 64)
#define O_WV1   (O_WHE + 36)
#define O_WSV1  (O_WV1 + 136)
#define O_BSV1  (O_WSV1 + 256)
#define O_W2H   (O_BSV1 + 4)
#define O_W2S   (O_W2H + 16)
#define O_B2    (O_W2S + 68*72)
#define O_WV2   (O_B2 + 64)
#define O_WSV2  (O_WV2 + 16)
#define O_BSV2  (O_WSV2 + 256)
#define O_W3H   (O_BSV2 + 4)
#define O_W3S   (O_W3H + 16)
#define O_B3    (O_W3S + 68*72)
#define O_WV3   (O_B3 + 64)
#define O_WSV3  (O_WV3 + 16)
#define O_BSV3  (O_WSV3 + 256)
#define SMEM_FLOATS (O_BSV3 + 4)
#define SMEM_BYTES (SMEM_FLOATS * 4)

typedef unsigned long long ull;

__device__ __forceinline__ float fsig(float x) {
    float t;
    asm("ex2.approx.f32 %0, %1;" : "=f"(t) : "f"(x * -1.4426950408889634f));
    float r;
    asm("rcp.approx.f32 %0, %1;" : "=f"(r) : "f"(t + 1.0f));
    return r;
}
__device__ __forceinline__ float fsqrt_(float x) {
    float r;
    asm("sqrt.approx.f32 %0, %1;" : "=f"(r) : "f"(x));
    return r;
}
__device__ __forceinline__ ull pack2(float lo, float hi) {
    ull r;
    asm("mov.b64 %0, {%1, %2};" : "=l"(r) : "f"(lo), "f"(hi));
    return r;
}
__device__ __forceinline__ void unpack2(float& lo, float& hi, ull a) {
    asm("mov.b64 {%0, %1}, %2;" : "=f"(lo), "=f"(hi) : "l"(a));
}
__device__ __forceinline__ ull add2(ull a, ull b) {
    ull r;
    asm("add.rn.f32x2 %0, %1, %2;" : "=l"(r) : "l"(a), "l"(b));
    return r;
}

__device__ __forceinline__ void fma_row32(ull acc[16], float x, const float* row) {
    ull xx = pack2(x, x);
    const ulonglong2* r2 = (const ulonglong2*)row;
#pragma unroll
    for (int j = 0; j < 8; j++) {
        ulonglong2 w = r2[j];
        asm("fma.rn.f32x2 %0, %1, %2, %0;" : "+l"(acc[2*j])   : "l"(xx), "l"(w.x));
        asm("fma.rn.f32x2 %0, %1, %2, %0;" : "+l"(acc[2*j+1]) : "l"(xx), "l"(w.y));
    }
}

// per-row vn body: norm, partner exchange, two weight-row FMAs, vo1 partials
__device__ __forceinline__ void vn_row(
    float x, float y, float z, int h, int hpk, int half,
    const float* sm, ull acc[16], float vo1p[12])
{
    float vn = fsqrt_(fmaxf(x*x + y*y + z*z, 1e-8f));
    float vnp = __shfl_xor_sync(0xffffffffu, vn, 1);
    fma_row32(acc, vn,  sm + O_WVN + h * 72 + half);
    fma_row32(acc, vnp, sm + O_WVN + hpk * 72 + half);
    float4 wv = *(const float4*)(sm + O_WV1 + h * 4);
    vo1p[0] += wv.x * x; vo1p[1]  += wv.x * y; vo1p[2]  += wv.x * z;
    vo1p[3] += wv.y * x; vo1p[4]  += wv.y * y; vo1p[5]  += wv.y * z;
    vo1p[6] += wv.z * x; vo1p[7]  += wv.z * y; vo1p[8]  += wv.z * z;
    vo1p[9] += wv.w * x; vo1p[10] += wv.w * y; vo1p[11] += wv.w * z;
}

// ---------------- GVP layer for layers 2/3 (64 scalars split over lane pair) ----------------
__device__ __forceinline__ void gvp64(
    int p, const float* sm, const float sf_in[32], const float vin[12],
    float sf_out[32], float vout[12],
    int o_wh, int o_ws, int o_b, int o_wv, int o_wsv, int o_bsv, bool final_)
{
    float vh[12];
#pragma unroll
    for (int h = 0; h < 4; h++) {
        float x = 0.f, y = 0.f, z = 0.f;
#pragma unroll
        for (int o = 0; o < 4; o++) {
            float w = sm[o_wh + o * 4 + h];
            x += vin[o*3+0] * w; y += vin[o*3+1] * w; z += vin[o*3+2] * w;
        }
        vh[h*3+0] = x; vh[h*3+1] = y; vh[h*3+2] = z;
    }
    float vn2[4];
#pragma unroll
    for (int h = 0; h < 4; h++)
        vn2[h] = fsqrt_(fmaxf(vh[h*3]*vh[h*3] + vh[h*3+1]*vh[h*3+1] + vh[h*3+2]*vh[h*3+2], 1e-8f));
    float vo2[12];
#pragma unroll
    for (int o = 0; o < 4; o++) {
        float x = 0.f, y = 0.f, z = 0.f;
#pragma unroll
        for (int h = 0; h < 4; h++) {
            float w = sm[o_wv + h * 4 + o];
            x += vh[h*3+0] * w; y += vh[h*3+1] * w; z += vh[h*3+2] * w;
        }
        vo2[o*3+0] = x; vo2[o*3+1] = y; vo2[o*3+2] = z;
    }
    ull acc[16];
    {
        const ulonglong2* B = (const ulonglong2*)(sm + o_b + 32 * p);
#pragma unroll
        for (int j = 0; j < 8; j++) {
            ulonglong2 b = B[j];
            acc[2*j]   = b.x;
            acc[2*j+1] = b.y;
        }
    }
    const float* W = sm + o_ws;
    int half = 36 * p;
#pragma unroll
    for (int r = 0; r < 32; r++) {
        float mine  = sf_in[r];
        float other = __shfl_xor_sync(0xffffffffu, mine, 1);
        float klo = p ? other : mine;
        float khi = p ? mine  : other;
        fma_row32(acc, klo, W + r * 72 + half);
        fma_row32(acc, khi, W + (32 + r) * 72 + half);
    }
#pragma unroll
    for (int h = 0; h < 4; h++)
        fma_row32(acc, vn2[h], W + (64 + h) * 72 + half);
#pragma unroll
    for (int j = 0; j < 16; j++) unpack2(sf_out[2*j], sf_out[2*j+1], acc[j]);

    ull P01 = 0, P23 = 0;
    {
        const ulonglong2* WSV = (const ulonglong2*)(sm + o_wsv + 32 * p * 4);
#pragma unroll
        for (int r = 0; r < 32; r++) {
            float t = final_ ? sf_out[r] : fsig(sf_out[r]);
            ull tt = pack2(t, t);
            ulonglong2 w = WSV[r];
            asm("fma.rn.f32x2 %0, %1, %2, %0;" : "+l"(P01) : "l"(tt), "l"(w.x));
            asm("fma.rn.f32x2 %0, %1, %2, %0;" : "+l"(P23) : "l"(tt), "l"(w.y));
        }
    }
    float p0, p1, p2, p3;
    unpack2(p0, p1, P01);
    unpack2(p2, p3, P23);
    float g0 = fsig(sm[o_bsv+0] + p0 + __shfl_xor_sync(0xffffffffu, p0, 1));
    float g1 = fsig(sm[o_bsv+1] + p1 + __shfl_xor_sync(0xffffffffu, p1, 1));
    float g2 = fsig(sm[o_bsv+2] + p2 + __shfl_xor_sync(0xffffffffu, p2, 1));
    float g3 = fsig(sm[o_bsv+3] + p3 + __shfl_xor_sync(0xffffffffu, p3, 1));
#pragma unroll
    for (int c = 0; c < 3; c++) {
        vout[0*3+c] = vo2[0*3+c] * g0;
        vout[1*3+c] = vo2[1*3+c] * g1;
        vout[2*3+c] = vo2[2*3+c] * g2;
        vout[3*3+c] = vo2[3*3+c] * g3;
    }
    if (!final_) {
#pragma unroll
        for (int r = 0; r < 32; r++) sf_out[r] = fmaxf(sf_out[r], 0.f);
    }
}

__device__ __forceinline__ void smcopy(float* d, const float* s, int n) {
    for (int i = threadIdx.x; i < n; i += blockDim.x) d[i] = s[i];
}
__device__ __forceinline__ void smcopy_pad(float* d, const float* s, int K) {
    for (int i = threadIdx.x; i < K * 64; i += blockDim.x) {
        int k = i >> 6, c = i & 63;
        d[k * 72 + c + (c >= 32 ? 4 : 0)] = s[i];
    }
}

// -------- prep: 16 nodes per block; folds bias; packed float3 ah; zeroes ticket --------
__global__ void __launch_bounds__(128) prep_kernel(
    const float* __restrict__ node_s, const float* __restrict__ node_v,
    const float* __restrict__ w1_wh, const float* __restrict__ w1_ws,
    const float* __restrict__ w1_wsb, int N)
{
    __shared__ float xs[16 * 128];
    const int tid = threadIdx.x;
    const int n0 = blockIdx.x * 16;
    const int nmax = min(16, N - n0);
    if (blockIdx.x == 0 && tid == 0) g_ticket = 0u;

    for (int i = tid; i < 16 * 128; i += 128) {
        int b = i >> 7;
        xs[i] = (b < nmax) ? node_s[(size_t)(n0 + b) * 128 + (i & 127)] : 0.f;
    }
    for (int i = tid; i < nmax * 64; i += 128) g_s_acc[(size_t)n0 * 64 + i] = 0.f;
    for (int i = tid; i < nmax * 12; i += 128) g_v_acc[(size_t)n0 * 12 + i] = 0.f;
    if (tid < nmax) g_cnt[n0 + tid] = 0.f;
    __syncthreads();

    {
        int j = tid & 63;
        int half = tid >> 6;
        const float* W = w1_ws + (half ? 160 * 64 : 0) + j;
        float bias = half ? 0.f : w1_wsb[j];
        float acc[16];
#pragma unroll
        for (int b = 0; b < 16; b++) acc[b] = 0.f;
        const float4* xs4 = (const float4*)xs;
#pragma unroll 2
        for (int k4 = 0; k4 < 32; k4++) {
            float w0 = W[(k4*4+0)*64], w1 = W[(k4*4+1)*64];
            float w2 = W[(k4*4+2)*64], w3 = W[(k4*4+3)*64];
#pragma unroll
            for (int b = 0; b < 16; b++) {
                float4 x = xs4[b * 32 + k4];
                acc[b] += x.x * w0 + x.y * w1 + x.z * w2 + x.w * w3;
            }
        }
        float* dst = half ? g_as_dst : g_as_src;
#pragma unroll
        for (int b = 0; b < 16; b++)
            if (b < nmax) dst[(size_t)(n0 + b) * 64 + j] = acc[b] + bias;
    }
    // ah: 16 nodes x 68 rows (34 src + 34 dst); row h -> chunk h/17, slot 3*(h%17)
    for (int i = tid; i < 16 * 68; i += 128) {
        int b = i / 68, r = i % 68;
        if (b >= nmax) continue;
        int n = n0 + b;
        bool is_src = (r < 34);
        int h = is_src ? r : r - 34;
        float x = 0.f, y = 0.f, z = 0.f;
        if (h < 33) {
            int base = is_src ? 0 : 17;
            const float* v = node_v + (size_t)n * 48;
#pragma unroll
            for (int k = 0; k < 16; k++) {
                float w = w1_wh[(base + k) * 33 + h];
                x += v[k*3+0] * w; y += v[k*3+1] * w; z += v[k*3+2] * w;
            }
        }
        int chunk = (h >= 17) ? 1 : 0;
        int k = h - 17 * chunk;
        float* dst = (is_src ? g_ah_src : g_ah_dst) + (size_t)n * 104 + chunk * 52 + 3 * k;
        dst[0] = x; dst[1] = y; dst[2] = z;
    }
}

// -------- main per-edge kernel: 2 lanes per edge, ticketed --------
__global__ void __launch_bounds__(128, 3) edge_kernel(
    const int* __restrict__ ei,
    const float* __restrict__ edge_s,
    const float* __restrict__ edge_v,
    const float* __restrict__ w1_wh, const float* __restrict__ w1_ws,
    const float* __restrict__ w1_wsb, const float* __restrict__ w1_wv,
    const float* __restrict__ w1_wsv, const float* __restrict__ w1_wsvb,
    const float* __restrict__ w2_wh, const float* __restrict__ w2_ws,
    const float* __restrict__ w2_wsb, const float* __restrict__ w2_wv,
    const float* __restrict__ w2_wsv, const float* __restrict__ w2_wsvb,
    const float* __restrict__ w3_wh, const float* __restrict__ w3_ws,
    const float* __restrict__ w3_wsb, const float* __restrict__ w3_wv,
    const float* __restrict__ w3_wsv, const float* __restrict__ w3_wsvb,
    int E)
{
    extern __shared__ float sm[];
    smcopy_pad(sm + O_WES, w1_ws + 128 * 64, 32);
    smcopy_pad(sm + O_WVN, w1_ws + 288 * 64, 33);
    for (int i = threadIdx.x; i < 72; i += blockDim.x) sm[O_WVN + 33 * 72 + i] = 0.f;
    smcopy(sm + O_B1,   w1_wsb, 64);
    smcopy(sm + O_WHE,  w1_wh + 16 * 33, 33);
    for (int i = threadIdx.x + 33; i < 36; i += blockDim.x) sm[O_WHE + i] = 0.f;
    smcopy(sm + O_WV1,  w1_wv, 132);
    for (int i = threadIdx.x + 132; i < 136; i += blockDim.x) sm[O_WV1 + i] = 0.f;
    smcopy(sm + O_WSV1, w1_wsv, 256);
    smcopy(sm + O_BSV1, w1_wsvb, 4);
    smcopy(sm + O_W2H,  w2_wh, 16);
    smcopy_pad(sm + O_W2S, w2_ws, 68);
    smcopy(sm + O_B2,   w2_wsb, 64);
    smcopy(sm + O_WV2,  w2_wv, 16);
    smcopy(sm + O_WSV2, w2_wsv, 256);
    smcopy(sm + O_BSV2, w2_wsvb, 4);
    smcopy(sm + O_W3H,  w3_wh, 16);
    smcopy_pad(sm + O_W3S, w3_ws, 68);
    smcopy(sm + O_B3,   w3_wsb, 64);
    smcopy(sm + O_WV3,  w3_wv, 16);
    smcopy(sm + O_WSV3, w3_wsv, 256);
    smcopy(sm + O_BSV3, w3_wsvb, 4);
    __syncthreads();

    const unsigned FULL = 0xffffffffu;
    const int lane = threadIdx.x & 31;
    const int p = lane & 1;
    const int wpair = lane >> 1;
    const int half = 36 * p;
    const int hs = 17 * p;
    const int hp = 17 - hs;

    unsigned t;
    {
        unsigned tt = 0;
        if (lane == 0) tt = atomicAdd(&g_ticket, 16u);
        t = __shfl_sync(FULL, tt, 0);
    }
    int P = (int)t + wpair;
    bool valid = P < E;
    int e = valid ? P : 0;
    int src = ei[e];
    int dst = ei[e + E];
    float ev0 = edge_v[e*3+0], ev1 = edge_v[e*3+1], ev2 = edge_v[e*3+2];

    while ((int)t < E) {
        unsigned t2;
        {
            unsigned tt = 0;
            if (lane == 0) tt = atomicAdd(&g_ticket, 16u);
            t2 = __shfl_sync(FULL, tt, 0);
        }
        int P2 = (int)t2 + wpair;
        bool valid2 = P2 < E;
        int e2 = valid2 ? P2 : 0;
        int src2 = ei[e2];
        int dst2 = ei[e2 + E];
        float f0 = edge_v[e2*3+0], f1 = edge_v[e2*3+1], f2 = edge_v[e2*3+2];

        // ---- layer 1 scalar acc init (bias pre-folded; packed adds)
        ull acc[16];
        {
            const ulonglong2* As = (const ulonglong2*)(g_as_src + (size_t)src * 64 + 32 * p);
            const ulonglong2* Bs = (const ulonglong2*)(g_as_dst + (size_t)dst * 64 + 32 * p);
#pragma unroll
            for (int j = 0; j < 8; j++) {
                ulonglong2 a = As[j], b = Bs[j];
                acc[2*j]   = add2(a.x, b.x);
                acc[2*j+1] = add2(a.y, b.y);
            }
        }
        // ---- edge_s rows
        {
            const float4* ES = (const float4*)(edge_s + (size_t)e * 32);
#pragma unroll
            for (int k4 = 0; k4 < 8; k4++) {
                float4 es = ES[k4];
                fma_row32(acc, es.x, sm + O_WES + (k4*4+0) * 72 + half);
                fma_row32(acc, es.y, sm + O_WES + (k4*4+1) * 72 + half);
                fma_row32(acc, es.z, sm + O_WES + (k4*4+2) * 72 + half);
                fma_row32(acc, es.w, sm + O_WES + (k4*4+3) * 72 + half);
            }
        }
        // ---- layer-1 vector path: packed float3 rows, 13 LDG.128 per side
        float vo1p[12];
#pragma unroll
        for (int i = 0; i < 12; i++) vo1p[i] = 0.f;
        {
            const ulonglong2* A4 = (const ulonglong2*)(g_ah_src + (size_t)src * 104 + 52 * p);
            const ulonglong2* B4 = (const ulonglong2*)(g_ah_dst + (size_t)dst * 104 + 52 * p);
#pragma unroll
            for (int g = 0; g < 4; g++) {
                float sfv[12];
#pragma unroll
                for (int q = 0; q < 3; q++) {
                    ulonglong2 aa = A4[g*3+q];
                    ulonglong2 bb = B4[g*3+q];
                    ull lo = add2(aa.x, bb.x);
                    ull hi = add2(aa.y, bb.y);
                    unpack2(sfv[q*4+0], sfv[q*4+1], lo);
                    unpack2(sfv[q*4+2], sfv[q*4+3], hi);
                }
#pragma unroll
                for (int kk = 0; kk < 4; kk++) {
                    int k = g * 4 + kk;
                    int h = hs + k;
                    float w = sm[O_WHE + h];
                    float x = fmaf(ev0, w, sfv[3*kk+0]);
                    float y = fmaf(ev1, w, sfv[3*kk+1]);
                    float z = fmaf(ev2, w, sfv[3*kk+2]);
                    vn_row(x, y, z, h, hp + k, half, sm, acc, vo1p);
                }
            }
            // row k = 16 (chunk's last; floats 48..50 of q12)
            {
                ulonglong2 aa = A4[12];
                ulonglong2 bb = B4[12];
                ull lo = add2(aa.x, bb.x);
                ull hi = add2(aa.y, bb.y);
                float s0, s1, s2, s3;
                unpack2(s0, s1, lo);
                unpack2(s2, s3, hi);
                int h = hs + 16;
                float w = sm[O_WHE + h];
                float x = fmaf(ev0, w, s0);
                float y = fmaf(ev1, w, s1);
                float z = fmaf(ev2, w, s2);
                vn_row(x, y, z, h, hp + 16, half, sm, acc, vo1p);
            }
        }
        float vo1[12];
#pragma unroll
        for (int i = 0; i < 12; i++)
            vo1[i] = vo1p[i] + __shfl_xor_sync(FULL, vo1p[i], 1);

        float s1f[32];
#pragma unroll
        for (int j = 0; j < 16; j++) unpack2(s1f[2*j], s1f[2*j+1], acc[j]);

        // ---- gate 1 (packed partials)
        float v1[12];
        {
            ull P01 = 0, P23 = 0;
            const ulonglong2* WSV = (const ulonglong2*)(sm + O_WSV1 + 32 * p * 4);
#pragma unroll
            for (int r = 0; r < 32; r++) {
                float tt = fsig(s1f[r]);
                ull tp = pack2(tt, tt);
                ulonglong2 w = WSV[r];
                asm("fma.rn.f32x2 %0, %1, %2, %0;" : "+l"(P01) : "l"(tp), "l"(w.x));
                asm("fma.rn.f32x2 %0, %1, %2, %0;" : "+l"(P23) : "l"(tp), "l"(w.y));
            }
            float p0, p1, p2, p3;
            unpack2(p0, p1, P01);
            unpack2(p2, p3, P23);
            float g0 = fsig(sm[O_BSV1+0] + p0 + __shfl_xor_sync(FULL, p0, 1));
            float g1 = fsig(sm[O_BSV1+1] + p1 + __shfl_xor_sync(FULL, p1, 1));
            float g2 = fsig(sm[O_BSV1+2] + p2 + __shfl_xor_sync(FULL, p2, 1));
            float g3 = fsig(sm[O_BSV1+3] + p3 + __shfl_xor_sync(FULL, p3, 1));
#pragma unroll
            for (int c = 0; c < 3; c++) {
                v1[0*3+c] = vo1[0*3+c] * g0;
                v1[1*3+c] = vo1[1*3+c] * g1;
                v1[2*3+c] = vo1[2*3+c] * g2;
                v1[3*3+c] = vo1[3*3+c] * g3;
            }
#pragma unroll
            for (int r = 0; r < 32; r++) s1f[r] = fmaxf(s1f[r], 0.f);
        }

        // ---- layers 2 and 3
        float s2f[32], v2[12];
        gvp64(p, sm, s1f, v1, s2f, v2, O_W2H, O_W2S, O_B2, O_WV2, O_WSV2, O_BSV2, false);
        float s3f[32], v3[12];
        gvp64(p, sm, s2f, v2, s3f, v3, O_W3H, O_W3S, O_B3, O_WV3, O_WSV3, O_BSV3, true);

        // ---- scatter-accumulate at dst
        if (valid) {
            float* sa = g_s_acc + (size_t)dst * 64 + 32 * p;
#pragma unroll
            for (int j = 0; j < 8; j++) {
                asm volatile("red.global.add.v4.f32 [%0], {%1, %2, %3, %4};"
                    :: "l"(sa + 4*j),
                       "f"(s3f[4*j]), "f"(s3f[4*j+1]), "f"(s3f[4*j+2]), "f"(s3f[4*j+3])
                    : "memory");
            }
            float* va = g_v_acc + (size_t)dst * 12 + 6 * p;
#pragma unroll
            for (int j = 0; j < 3; j++) {
                asm volatile("red.global.add.v2.f32 [%0], {%1, %2};"
                    :: "l"(va + 2*j), "f"(v3[6*p + 2*j]), "f"(v3[6*p + 2*j+1])
                    : "memory");
            }
            if (p == 0) atomicAdd(g_cnt + dst, 1.0f);
        }

        t = t2; e = e2; src = src2; dst = dst2;
        ev0 = f0; ev1 = f1; ev2 = f2; valid = valid2;
    }
}

// -------- finalize (fast-math intrinsics) --------
__global__ void finalize_kernel(const int* __restrict__ mask,
                                float* __restrict__ out, int N)
{
    int idx = blockIdx.x * blockDim.x + threadIdx.x;
    int total = N * 64 + N * 4;
    if (idx >= total) return;
    if (idx < N * 64) {
        int n = idx >> 6;
        int j = idx & 63;
        float denom = fmaxf(g_cnt[n], 1.0f);
        float s = g_s_acc[idx] / denom;
        float m = (mask[n] != 0) ? 1.0f : 0.0f;
        float val;
        if (j < 7)       val = __cosf(s);
        else if (j < 14) val = __sinf(s);
        else             val = __expf(s);
        out[idx] = val * m;
    } else {
        int k = idx - N * 64;
        int n = k >> 2;
        int o = k & 3;
        float denom = fmaxf(g_cnt[n], 1.0f);
        float x = g_v_acc[n*12 + o*3 + 0] / denom;
        float y = g_v_acc[n*12 + o*3 + 1] / denom;
        float z = g_v_acc[n*12 + o*3 + 2] / denom;
        float mag = sqrtf(x*x + y*y + z*z);
        float m = (mask[n] != 0) ? 1.0f : 0.0f;
        float sc = m / (mag + 1e-8f);
        float* vout = out + N * 64 + n * 12 + o * 3;
        vout[0] = x * sc; vout[1] = y * sc; vout[2] = z * sc;
    }
}

extern "C" void kernel_launch(void* const* d_in, const int* in_sizes, int n_in,
                              void* d_out, int out_size)
{
    const float* node_s = (const float*)d_in[0];
    const float* node_v = (const float*)d_in[1];
    const int*   ei     = (const int*)d_in[2];
    const float* edge_s = (const float*)d_in[3];
    const float* edge_v = (const float*)d_in[4];
    const int*   mask   = (const int*)d_in[5];
    const float* w1_wh  = (const float*)d_in[6];
    const float* w1_ws  = (const float*)d_in[7];
    const float* w1_wsb = (const float*)d_in[8];

    int N = in_sizes[0] / 128;
    int E = in_sizes[3] / 32;
    float* out = (float*)d_out;

    prep_kernel<<<(N + 15) / 16, 128>>>(node_s, node_v, w1_wh, w1_ws, w1_wsb, N);

    cudaFuncSetAttribute(edge_kernel,
                         cudaFuncAttributeMaxDynamicSharedMemorySize, SMEM_BYTES);
    edge_kernel<<<444, 128, SMEM_BYTES>>>(
        ei, edge_s, edge_v,
        w1_wh, w1_ws, w1_wsb,
        (const float*)d_in[9],  (const float*)d_in[10],
        (const float*)d_in[11], (const float*)d_in[12], (const float*)d_in[13],
        (const float*)d_in[14], (const float*)d_in[15], (const float*)d_in[16],
        (const float*)d_in[17], (const float*)d_in[18], (const float*)d_in[19],
        (const float*)d_in[20], (const float*)d_in[21], (const float*)d_in[22],
        (const float*)d_in[23],
        E);

    finalize_kernel<<<(N * 68 + 255) / 256, 256>>>(mask, out, N);
}

// round 17
// speedup vs baseline: 1.0635x; 1.0120x over previous
#include <cuda_runtime.h>
#include <math.h>
#include <stdint.h>

#define MAXN 20000

// ---------------- scratch (static device memory; no allocs) ----------------
// ah layout: per node, 2 lane-chunks of 52 floats (17 rows x 3 floats + 1 pad),
// chunk c holds rows 17c..17c+16 (row 33 is zero pad). 16B-aligned chunks.
__device__ float  g_ah_src[MAXN * 104];
__device__ float  g_ah_dst[MAXN * 104];
__device__ float  g_as_src[MAXN * 64];   // includes folded w1_wsb bias
__device__ float  g_as_dst[MAXN * 64];
__device__ float  g_s_acc[MAXN * 64];
__device__ float  g_v_acc[MAXN * 12];
__device__ float  g_cnt[MAXN];
__device__ unsigned g_ticket;

// ---------------- shared-memory weight layout (float indices) ----------------
#define O_WES   0
#define O_WVN   (O_WES + 32*72)
#define O_B1    (O_WVN + 34*72)
#define O_WHE   (O_B1 + 64)
#define O_WV1   (O_WHE + 36)
#define O_WSV1  (O_WV1 + 136)
#define O_BSV1  (O_WSV1 + 256)
#define O_W2H   (O_BSV1 + 4)
#define O_W2S   (O_W2H + 16)
#define O_B2    (O_W2S + 68*72)
#define O_WV2   (O_B2 + 64)
#define O_WSV2  (O_WV2 + 16)
#define O_BSV2  (O_WSV2 + 256)
#define O_W3H   (O_BSV2 + 4)
#define O_W3S   (O_W3H + 16)
#define O_B3    (O_W3S + 68*72)
#define O_WV3   (O_B3 + 64)
#define O_WSV3  (O_WV3 + 16)
#define O_BSV3  (O_WSV3 + 256)
#define SMEM_FLOATS (O_BSV3 + 4)
#define SMEM_BYTES (SMEM_FLOATS * 4)

typedef unsigned long long ull;

__device__ __forceinline__ float fsig(float x) {
    float t;
    asm("ex2.approx.f32 %0, %1;" : "=f"(t) : "f"(x * -1.4426950408889634f));
    float r;
    asm("rcp.approx.f32 %0, %1;" : "=f"(r) : "f"(t + 1.0f));
    return r;
}
__device__ __forceinline__ float fsqrt_(float x) {
    float r;
    asm("sqrt.approx.f32 %0, %1;" : "=f"(r) : "f"(x));
    return r;
}
__device__ __forceinline__ ull pack2(float lo, float hi) {
    ull r;
    asm("mov.b64 %0, {%1, %2};" : "=l"(r) : "f"(lo), "f"(hi));
    return r;
}
__device__ __forceinline__ void unpack2(float& lo, float& hi, ull a) {
    asm("mov.b64 {%0, %1}, %2;" : "=f"(lo), "=f"(hi) : "l"(a));
}
__device__ __forceinline__ ull add2(ull a, ull b) {
    ull r;
    asm("add.rn.f32x2 %0, %1, %2;" : "=l"(r) : "l"(a), "l"(b));
    return r;
}

__device__ __forceinline__ void fma_row32(ull acc[16], float x, const float* row) {
    ull xx = pack2(x, x);
    const ulonglong2* r2 = (const ulonglong2*)row;
#pragma unroll
    for (int j = 0; j < 8; j++) {
        ulonglong2 w = r2[j];
        asm("fma.rn.f32x2 %0, %1, %2, %0;" : "+l"(acc[2*j])   : "l"(xx), "l"(w.x));
        asm("fma.rn.f32x2 %0, %1, %2, %0;" : "+l"(acc[2*j+1]) : "l"(xx), "l"(w.y));
    }
}

// per-row vn body: norm, partner exchange, two weight-row FMAs, vo1 partials
__device__ __forceinline__ void vn_row(
    float x, float y, float z, int h, int hpk, int half,
    const float* sm, ull acc[16], float vo1p[12])
{
    float vn = fsqrt_(fmaxf(x*x + y*y + z*z, 1e-8f));
    float vnp = __shfl_xor_sync(0xffffffffu, vn, 1);
    fma_row32(acc, vn,  sm + O_WVN + h * 72 + half);
    fma_row32(acc, vnp, sm + O_WVN + hpk * 72 + half);
    float4 wv = *(const float4*)(sm + O_WV1 + h * 4);
    vo1p[0] += wv.x * x; vo1p[1]  += wv.x * y; vo1p[2]  += wv.x * z;
    vo1p[3] += wv.y * x; vo1p[4]  += wv.y * y; vo1p[5]  += wv.y * z;
    vo1p[6] += wv.z * x; vo1p[7]  += wv.z * y; vo1p[8]  += wv.z * z;
    vo1p[9] += wv.w * x; vo1p[10] += wv.w * y; vo1p[11] += wv.w * z;
}

// ---------------- GVP layer for layers 2/3 (64 scalars split over lane pair) ----------------
__device__ __forceinline__ void gvp64(
    int p, const float* sm, const float sf_in[32], const float vin[12],
    float sf_out[32], float vout[12],
    int o_wh, int o_ws, int o_b, int o_wv, int o_wsv, int o_bsv, bool final_)
{
    float vh[12];
#pragma unroll
    for (int h = 0; h < 4; h++) {
        float x = 0.f, y = 0.f, z = 0.f;
#pragma unroll
        for (int o = 0; o < 4; o++) {
            float w = sm[o_wh + o * 4 + h];
            x += vin[o*3+0] * w; y += vin[o*3+1] * w; z += vin[o*3+2] * w;
        }
        vh[h*3+0] = x; vh[h*3+1] = y; vh[h*3+2] = z;
    }
    float vn2[4];
#pragma unroll
    for (int h = 0; h < 4; h++)
        vn2[h] = fsqrt_(fmaxf(vh[h*3]*vh[h*3] + vh[h*3+1]*vh[h*3+1] + vh[h*3+2]*vh[h*3+2], 1e-8f));
    float vo2[12];
#pragma unroll
    for (int o = 0; o < 4; o++) {
        float x = 0.f, y = 0.f, z = 0.f;
#pragma unroll
        for (int h = 0; h < 4; h++) {
            float w = sm[o_wv + h * 4 + o];
            x += vh[h*3+0] * w; y += vh[h*3+1] * w; z += vh[h*3+2] * w;
        }
        vo2[o*3+0] = x; vo2[o*3+1] = y; vo2[o*3+2] = z;
    }
    ull acc[16];
    {
        const ulonglong2* B = (const ulonglong2*)(sm + o_b + 32 * p);
#pragma unroll
        for (int j = 0; j < 8; j++) {
            ulonglong2 b = B[j];
            acc[2*j]   = b.x;
            acc[2*j+1] = b.y;
        }
    }
    const float* W = sm + o_ws;
    int half = 36 * p;
#pragma unroll
    for (int r = 0; r < 32; r++) {
        float mine  = sf_in[r];
        float other = __shfl_xor_sync(0xffffffffu, mine, 1);
        float klo = p ? other : mine;
        float khi = p ? mine  : other;
        fma_row32(acc, klo, W + r * 72 + half);
        fma_row32(acc, khi, W + (32 + r) * 72 + half);
    }
#pragma unroll
    for (int h = 0; h < 4; h++)
        fma_row32(acc, vn2[h], W + (64 + h) * 72 + half);
#pragma unroll
    for (int j = 0; j < 16; j++) unpack2(sf_out[2*j], sf_out[2*j+1], acc[j]);

    ull P01 = 0, P23 = 0;
    {
        const ulonglong2* WSV = (const ulonglong2*)(sm + o_wsv + 32 * p * 4);
#pragma unroll
        for (int r = 0; r < 32; r++) {
            float t = final_ ? sf_out[r] : fsig(sf_out[r]);
            ull tt = pack2(t, t);
            ulonglong2 w = WSV[r];
            asm("fma.rn.f32x2 %0, %1, %2, %0;" : "+l"(P01) : "l"(tt), "l"(w.x));
            asm("fma.rn.f32x2 %0, %1, %2, %0;" : "+l"(P23) : "l"(tt), "l"(w.y));
        }
    }
    float p0, p1, p2, p3;
    unpack2(p0, p1, P01);
    unpack2(p2, p3, P23);
    float g0 = fsig(sm[o_bsv+0] + p0 + __shfl_xor_sync(0xffffffffu, p0, 1));
    float g1 = fsig(sm[o_bsv+1] + p1 + __shfl_xor_sync(0xffffffffu, p1, 1));
    float g2 = fsig(sm[o_bsv+2] + p2 + __shfl_xor_sync(0xffffffffu, p2, 1));
    float g3 = fsig(sm[o_bsv+3] + p3 + __shfl_xor_sync(0xffffffffu, p3, 1));
#pragma unroll
    for (int c = 0; c < 3; c++) {
        vout[0*3+c] = vo2[0*3+c] * g0;
        vout[1*3+c] = vo2[1*3+c] * g1;
        vout[2*3+c] = vo2[2*3+c] * g2;
        vout[3*3+c] = vo2[3*3+c] * g3;
    }
    if (!final_) {
#pragma unroll
        for (int r = 0; r < 32; r++) sf_out[r] = fmaxf(sf_out[r], 0.f);
    }
}

__device__ __forceinline__ void smcopy(float* d, const float* s, int n) {
    for (int i = threadIdx.x; i < n; i += blockDim.x) d[i] = s[i];
}
__device__ __forceinline__ void smcopy_pad(float* d, const float* s, int K) {
    for (int i = threadIdx.x; i < K * 64; i += blockDim.x) {
        int k = i >> 6, c = i & 63;
        d[k * 72 + c + (c >= 32 ? 4 : 0)] = s[i];
    }
}

// -------- prep: 16 nodes per block; folds bias; packed float3 ah; zeroes ticket --------
__global__ void __launch_bounds__(128) prep_kernel(
    const float* __restrict__ node_s, const float* __restrict__ node_v,
    const float* __restrict__ w1_wh, const float* __restrict__ w1_ws,
    const float* __restrict__ w1_wsb, int N)
{
    __shared__ float xs[16 * 128];
    const int tid = threadIdx.x;
    const int n0 = blockIdx.x * 16;
    const int nmax = min(16, N - n0);
    if (blockIdx.x == 0 && tid == 0) g_ticket = 0u;

    for (int i = tid; i < 16 * 128; i += 128) {
        int b = i >> 7;
        xs[i] = (b < nmax) ? node_s[(size_t)(n0 + b) * 128 + (i & 127)] : 0.f;
    }
    for (int i = tid; i < nmax * 64; i += 128) g_s_acc[(size_t)n0 * 64 + i] = 0.f;
    for (int i = tid; i < nmax * 12; i += 128) g_v_acc[(size_t)n0 * 12 + i] = 0.f;
    if (tid < nmax) g_cnt[n0 + tid] = 0.f;
    __syncthreads();

    {
        int j = tid & 63;
        int half = tid >> 6;
        const float* W = w1_ws + (half ? 160 * 64 : 0) + j;
        float bias = half ? 0.f : w1_wsb[j];
        float acc[16];
#pragma unroll
        for (int b = 0; b < 16; b++) acc[b] = 0.f;
        const float4* xs4 = (const float4*)xs;
#pragma unroll 2
        for (int k4 = 0; k4 < 32; k4++) {
            float w0 = W[(k4*4+0)*64], w1 = W[(k4*4+1)*64];
            float w2 = W[(k4*4+2)*64], w3 = W[(k4*4+3)*64];
#pragma unroll
            for (int b = 0; b < 16; b++) {
                float4 x = xs4[b * 32 + k4];
                acc[b] += x.x * w0 + x.y * w1 + x.z * w2 + x.w * w3;
            }
        }
        float* dst = half ? g_as_dst : g_as_src;
#pragma unroll
        for (int b = 0; b < 16; b++)
            if (b < nmax) dst[(size_t)(n0 + b) * 64 + j] = acc[b] + bias;
    }
    // ah: 16 nodes x 68 rows (34 src + 34 dst); row h -> chunk h/17, slot 3*(h%17)
    for (int i = tid; i < 16 * 68; i += 128) {
        int b = i / 68, r = i % 68;
        if (b >= nmax) continue;
        int n = n0 + b;
        bool is_src = (r < 34);
        int h = is_src ? r : r - 34;
        float x = 0.f, y = 0.f, z = 0.f;
        if (h < 33) {
            int base = is_src ? 0 : 17;
            const float* v = node_v + (size_t)n * 48;
#pragma unroll
            for (int k = 0; k < 16; k++) {
                float w = w1_wh[(base + k) * 33 + h];
                x += v[k*3+0] * w; y += v[k*3+1] * w; z += v[k*3+2] * w;
            }
        }
        int chunk = (h >= 17) ? 1 : 0;
        int k = h - 17 * chunk;
        float* dst = (is_src ? g_ah_src : g_ah_dst) + (size_t)n * 104 + chunk * 52 + 3 * k;
        dst[0] = x; dst[1] = y; dst[2] = z;
    }
}

// -------- main per-edge kernel: 2 lanes per edge, ticketed (32 edges/ticket) --------
__global__ void __launch_bounds__(128, 3) edge_kernel(
    const int* __restrict__ ei,
    const float* __restrict__ edge_s,
    const float* __restrict__ edge_v,
    const float* __restrict__ w1_wh, const float* __restrict__ w1_ws,
    const float* __restrict__ w1_wsb, const float* __restrict__ w1_wv,
    const float* __restrict__ w1_wsv, const float* __restrict__ w1_wsvb,
    const float* __restrict__ w2_wh, const float* __restrict__ w2_ws,
    const float* __restrict__ w2_wsb, const float* __restrict__ w2_wv,
    const float* __restrict__ w2_wsv, const float* __restrict__ w2_wsvb,
    const float* __restrict__ w3_wh, const float* __restrict__ w3_ws,
    const float* __restrict__ w3_wsb, const float* __restrict__ w3_wv,
    const float* __restrict__ w3_wsv, const float* __restrict__ w3_wsvb,
    int E)
{
    extern __shared__ float sm[];
    smcopy_pad(sm + O_WES, w1_ws + 128 * 64, 32);
    smcopy_pad(sm + O_WVN, w1_ws + 288 * 64, 33);
    for (int i = threadIdx.x; i < 72; i += blockDim.x) sm[O_WVN + 33 * 72 + i] = 0.f;
    smcopy(sm + O_WHE,  w1_wh + 16 * 33, 33);
    for (int i = threadIdx.x + 33; i < 36; i += blockDim.x) sm[O_WHE + i] = 0.f;
    smcopy(sm + O_WV1,  w1_wv, 132);
    for (int i = threadIdx.x + 132; i < 136; i += blockDim.x) sm[O_WV1 + i] = 0.f;
    smcopy(sm + O_WSV1, w1_wsv, 256);
    smcopy(sm + O_BSV1, w1_wsvb, 4);
    smcopy(sm + O_W2H,  w2_wh, 16);
    smcopy_pad(sm + O_W2S, w2_ws, 68);
    smcopy(sm + O_B2,   w2_wsb, 64);
    smcopy(sm + O_WV2,  w2_wv, 16);
    smcopy(sm + O_WSV2, w2_wsv, 256);
    smcopy(sm + O_BSV2, w2_wsvb, 4);
    smcopy(sm + O_W3H,  w3_wh, 16);
    smcopy_pad(sm + O_W3S, w3_ws, 68);
    smcopy(sm + O_B3,   w3_wsb, 64);
    smcopy(sm + O_WV3,  w3_wv, 16);
    smcopy(sm + O_WSV3, w3_wsv, 256);
    smcopy(sm + O_BSV3, w3_wsvb, 4);
    __syncthreads();

    const unsigned FULL = 0xffffffffu;
    const int lane = threadIdx.x & 31;
    const int p = lane & 1;
    const int wpair = lane >> 1;
    const int half = 36 * p;
    const int hs = 17 * p;
    const int hp = 17 - hs;

    // warp-uniform ticket fetch (32 edges per ticket: 2 sub-rounds of 16)
    unsigned t;
    {
        unsigned tt = 0;
        if (lane == 0) tt = atomicAdd(&g_ticket, 32u);
        t = __shfl_sync(FULL, tt, 0);
    }
    int sub = 0;
    int P = (int)t + wpair;
    bool valid = P < E;
    int e = valid ? P : 0;
    int src = ei[e];
    int dst = ei[e + E];
    float ev0 = edge_v[e*3+0], ev1 = edge_v[e*3+1], ev2 = edge_v[e*3+2];

    while ((int)t + sub * 16 < E) {
        // next work item: second half of this ticket, or a fresh ticket
        unsigned t2;
        int sub2;
        if (sub == 0) {
            t2 = t; sub2 = 1;
        } else {
            unsigned tt = 0;
            if (lane == 0) tt = atomicAdd(&g_ticket, 32u);
            t2 = __shfl_sync(FULL, tt, 0);
            sub2 = 0;
        }
        int P2 = (int)t2 + sub2 * 16 + wpair;
        bool valid2 = P2 < E;
        int e2 = valid2 ? P2 : 0;
        int src2 = ei[e2];
        int dst2 = ei[e2 + E];
        float f0 = edge_v[e2*3+0], f1 = edge_v[e2*3+1], f2 = edge_v[e2*3+2];

        // ---- layer 1 scalar acc init (bias pre-folded; packed adds)
        ull acc[16];
        {
            const ulonglong2* As = (const ulonglong2*)(g_as_src + (size_t)src * 64 + 32 * p);
            const ulonglong2* Bs = (const ulonglong2*)(g_as_dst + (size_t)dst * 64 + 32 * p);
#pragma unroll
            for (int j = 0; j < 8; j++) {
                ulonglong2 a = As[j], b = Bs[j];
                acc[2*j]   = add2(a.x, b.x);
                acc[2*j+1] = add2(a.y, b.y);
            }
        }
        // ---- edge_s rows
        {
            const float4* ES = (const float4*)(edge_s + (size_t)e * 32);
#pragma unroll
            for (int k4 = 0; k4 < 8; k4++) {
                float4 es = ES[k4];
                fma_row32(acc, es.x, sm + O_WES + (k4*4+0) * 72 + half);
                fma_row32(acc, es.y, sm + O_WES + (k4*4+1) * 72 + half);
                fma_row32(acc, es.z, sm + O_WES + (k4*4+2) * 72 + half);
                fma_row32(acc, es.w, sm + O_WES + (k4*4+3) * 72 + half);
            }
        }
        // ---- layer-1 vector path: packed float3 rows, 13 LDG.128 per side
        float vo1p[12];
#pragma unroll
        for (int i = 0; i < 12; i++) vo1p[i] = 0.f;
        {
            const ulonglong2* A4 = (const ulonglong2*)(g_ah_src + (size_t)src * 104 + 52 * p);
            const ulonglong2* B4 = (const ulonglong2*)(g_ah_dst + (size_t)dst * 104 + 52 * p);
#pragma unroll
            for (int g = 0; g < 4; g++) {
                float sfv[12];
#pragma unroll
                for (int q = 0; q < 3; q++) {
                    ulonglong2 aa = A4[g*3+q];
                    ulonglong2 bb = B4[g*3+q];
                    ull lo = add2(aa.x, bb.x);
                    ull hi = add2(aa.y, bb.y);
                    unpack2(sfv[q*4+0], sfv[q*4+1], lo);
                    unpack2(sfv[q*4+2], sfv[q*4+3], hi);
                }
#pragma unroll
                for (int kk = 0; kk < 4; kk++) {
                    int k = g * 4 + kk;
                    int h = hs + k;
                    float w = sm[O_WHE + h];
                    float x = fmaf(ev0, w, sfv[3*kk+0]);
                    float y = fmaf(ev1, w, sfv[3*kk+1]);
                    float z = fmaf(ev2, w, sfv[3*kk+2]);
                    vn_row(x, y, z, h, hp + k, half, sm, acc, vo1p);
                }
            }
            {
                ulonglong2 aa = A4[12];
                ulonglong2 bb = B4[12];
                ull lo = add2(aa.x, bb.x);
                ull hi = add2(aa.y, bb.y);
                float s0, s1, s2, s3;
                unpack2(s0, s1, lo);
                unpack2(s2, s3, hi);
                int h = hs + 16;
                float w = sm[O_WHE + h];
                float x = fmaf(ev0, w, s0);
                float y = fmaf(ev1, w, s1);
                float z = fmaf(ev2, w, s2);
                vn_row(x, y, z, h, hp + 16, half, sm, acc, vo1p);
            }
        }
        float vo1[12];
#pragma unroll
        for (int i = 0; i < 12; i++)
            vo1[i] = vo1p[i] + __shfl_xor_sync(FULL, vo1p[i], 1);

        float s1f[32];
#pragma unroll
        for (int j = 0; j < 16; j++) unpack2(s1f[2*j], s1f[2*j+1], acc[j]);

        // ---- gate 1 (packed partials)
        float v1[12];
        {
            ull P01 = 0, P23 = 0;
            const ulonglong2* WSV = (const ulonglong2*)(sm + O_WSV1 + 32 * p * 4);
#pragma unroll
            for (int r = 0; r < 32; r++) {
                float tt = fsig(s1f[r]);
                ull tp = pack2(tt, tt);
                ulonglong2 w = WSV[r];
                asm("fma.rn.f32x2 %0, %1, %2, %0;" : "+l"(P01) : "l"(tp), "l"(w.x));
                asm("fma.rn.f32x2 %0, %1, %2, %0;" : "+l"(P23) : "l"(tp), "l"(w.y));
            }
            float p0, p1, p2, p3;
            unpack2(p0, p1, P01);
            unpack2(p2, p3, P23);
            float g0 = fsig(sm[O_BSV1+0] + p0 + __shfl_xor_sync(FULL, p0, 1));
            float g1 = fsig(sm[O_BSV1+1] + p1 + __shfl_xor_sync(FULL, p1, 1));
            float g2 = fsig(sm[O_BSV1+2] + p2 + __shfl_xor_sync(FULL, p2, 1));
            float g3 = fsig(sm[O_BSV1+3] + p3 + __shfl_xor_sync(FULL, p3, 1));
#pragma unroll
            for (int c = 0; c < 3; c++) {
                v1[0*3+c] = vo1[0*3+c] * g0;
                v1[1*3+c] = vo1[1*3+c] * g1;
                v1[2*3+c] = vo1[2*3+c] * g2;
                v1[3*3+c] = vo1[3*3+c] * g3;
            }
#pragma unroll
            for (int r = 0; r < 32; r++) s1f[r] = fmaxf(s1f[r], 0.f);
        }

        // ---- layers 2 and 3
        float s2f[32], v2[12];
        gvp64(p, sm, s1f, v1, s2f, v2, O_W2H, O_W2S, O_B2, O_WV2, O_WSV2, O_BSV2, false);
        float s3f[32], v3[12];
        gvp64(p, sm, s2f, v2, s3f, v3, O_W3H, O_W3S, O_B3, O_WV3, O_WSV3, O_BSV3, true);

        // ---- scatter-accumulate at dst
        if (valid) {
            float* sa = g_s_acc + (size_t)dst * 64 + 32 * p;
#pragma unroll
            for (int j = 0; j < 8; j++) {
                asm volatile("red.global.add.v4.f32 [%0], {%1, %2, %3, %4};"
                    :: "l"(sa + 4*j),
                       "f"(s3f[4*j]), "f"(s3f[4*j+1]), "f"(s3f[4*j+2]), "f"(s3f[4*j+3])
                    : "memory");
            }
            float* va = g_v_acc + (size_t)dst * 12 + 6 * p;
#pragma unroll
            for (int j = 0; j < 3; j++) {
                asm volatile("red.global.add.v2.f32 [%0], {%1, %2};"
                    :: "l"(va + 2*j), "f"(v3[6*p + 2*j]), "f"(v3[6*p + 2*j+1])
                    : "memory");
            }
            if (p == 0) atomicAdd(g_cnt + dst, 1.0f);
        }

        t = t2; sub = sub2; e = e2; src = src2; dst = dst2;
        ev0 = f0; ev1 = f1; ev2 = f2; valid = valid2;
    }
}

// -------- finalize (fast-math intrinsics) --------
__global__ void finalize_kernel(const int* __restrict__ mask,
                                float* __restrict__ out, int N)
{
    int idx = blockIdx.x * blockDim.x + threadIdx.x;
    int total = N * 64 + N * 4;
    if (idx >= total) return;
    if (idx < N * 64) {
        int n = idx >> 6;
        int j = idx & 63;
        float denom = fmaxf(g_cnt[n], 1.0f);
        float s = g_s_acc[idx] / denom;
        float m = (mask[n] != 0) ? 1.0f : 0.0f;
        float val;
        if (j < 7)       val = __cosf(s);
        else if (j < 14) val = __sinf(s);
        else             val = __expf(s);
        out[idx] = val * m;
    } else {
        int k = idx - N * 64;
        int n = k >> 2;
        int o = k & 3;
        float denom = fmaxf(g_cnt[n], 1.0f);
        float x = g_v_acc[n*12 + o*3 + 0] / denom;
        float y = g_v_acc[n*12 + o*3 + 1] / denom;
        float z = g_v_acc[n*12 + o*3 + 2] / denom;
        float mag = sqrtf(x*x + y*y + z*z);
        float m = (mask[n] != 0) ? 1.0f : 0.0f;
        float sc = m / (mag + 1e-8f);
        float* vout = out + N * 64 + n * 12 + o * 3;
        vout[0] = x * sc; vout[1] = y * sc; vout[2] = z * sc;
    }
}

extern "C" void kernel_launch(void* const* d_in, const int* in_sizes, int n_in,
                              void* d_out, int out_size)
{
    const float* node_s = (const float*)d_in[0];
    const float* node_v = (const float*)d_in[1];
    const int*   ei     = (const int*)d_in[2];
    const float* edge_s = (const float*)d_in[3];
    const float* edge_v = (const float*)d_in[4];
    const int*   mask   = (const int*)d_in[5];
    const float* w1_wh  = (const float*)d_in[6];
    const float* w1_ws  = (const float*)d_in[7];
    const float* w1_wsb = (const float*)d_in[8];

    int N = in_sizes[0] / 128;
    int E = in_sizes[3] / 32;
    float* out = (float*)d_out;

    prep_kernel<<<(N + 15) / 16, 128>>>(node_s, node_v, w1_wh, w1_ws, w1_wsb, N);

    cudaFuncSetAttribute(edge_kernel,
                         cudaFuncAttributeMaxDynamicSharedMemorySize, SMEM_BYTES);
    edge_kernel<<<444, 128, SMEM_BYTES>>>(
        ei, edge_s, edge_v,
        w1_wh, w1_ws, w1_wsb,
        (const float*)d_in[9],  (const float*)d_in[10],
        (const float*)d_in[11], (const float*)d_in[12], (const float*)d_in[13],
        (const float*)d_in[14], (const float*)d_in[15], (const float*)d_in[16],
        (const float*)d_in[17], (const float*)d_in[18], (const float*)d_in[19],
        (const float*)d_in[20], (const float*)d_in[21], (const float*)d_in[22],
        (const float*)d_in[23],
        E);

    finalize_kernel<<<(N * 68 + 255) / 256, 256>>>(mask, out, N);
}